// round 2
// baseline (speedup 1.0000x reference)
#include <cuda_runtime.h>

// ---------------------------------------------------------------------------
// Problem constants
// ---------------------------------------------------------------------------
#define P_ 64
#define N_ 2048
#define M1_ 512
#define M2_ 128
#define K_ 32

// Output packing offsets (float32 elements, reference tuple order)
#define XG_OFF      0            // [64,768]
#define POSG_OFF    49152        // [64,3] zeros
#define BATCHG_OFF  49344        // [64]
#define X2_OFF      49408        // [8192,384]
#define Q2_OFF      3195136      // [8192,3]
#define BATCH2_OFF  3219712     // [8192]
#define VMIN_OFF    3227904      // [64,3]
#define DIFF_OFF    3228096      // [64]

// ---------------------------------------------------------------------------
// Scratch (device globals; no allocations allowed)
// ---------------------------------------------------------------------------
__device__ float g_pn   [P_ * N_ * 3];
__device__ float g_q1   [P_ * M1_ * 3];
__device__ int   g_nidx1[P_ * M1_ * K_];
__device__ int   g_cnt1 [P_ * M1_];
__device__ float g_x1   [P_ * M1_ * 128];
__device__ int   g_nidx2[P_ * M2_ * K_];
__device__ int   g_cnt2 [P_ * M2_];

// ---------------------------------------------------------------------------
// Exact (non-fused) squared distance: ((dx*dx + dy*dy) + dz*dz)
// Matches XLA square-then-reduce lowering (no FMA contraction).
// ---------------------------------------------------------------------------
__device__ __forceinline__ float dist2e(float ax, float ay, float az,
                                        float bx, float by, float bz) {
    float dx = __fsub_rn(ax, bx);
    float dy = __fsub_rn(ay, by);
    float dz = __fsub_rn(az, bz);
    float s  = __fadd_rn(__fmul_rn(dx, dx), __fmul_rn(dy, dy));
    return __fadd_rn(s, __fmul_rn(dz, dz));
}

// ---------------------------------------------------------------------------
// Kernel 1: per-patch normalization + small pass-through outputs + zero xg
// ---------------------------------------------------------------------------
__global__ __launch_bounds__(256) void norm_kernel(const float* __restrict__ pos,
                                                   float* __restrict__ out) {
    int p = blockIdx.x, t = threadIdx.x;
    const float* base = pos + (size_t)p * N_ * 3;

    float mn0 = 3.4e38f, mn1 = 3.4e38f, mn2 = 3.4e38f;
    float mx0 = -3.4e38f, mx1 = -3.4e38f, mx2 = -3.4e38f;
    for (int i = t; i < N_; i += 256) {
        float v0 = base[i * 3 + 0], v1 = base[i * 3 + 1], v2 = base[i * 3 + 2];
        mn0 = fminf(mn0, v0); mx0 = fmaxf(mx0, v0);
        mn1 = fminf(mn1, v1); mx1 = fmaxf(mx1, v1);
        mn2 = fminf(mn2, v2); mx2 = fmaxf(mx2, v2);
    }
#pragma unroll
    for (int o = 16; o; o >>= 1) {
        mn0 = fminf(mn0, __shfl_down_sync(0xffffffffu, mn0, o));
        mn1 = fminf(mn1, __shfl_down_sync(0xffffffffu, mn1, o));
        mn2 = fminf(mn2, __shfl_down_sync(0xffffffffu, mn2, o));
        mx0 = fmaxf(mx0, __shfl_down_sync(0xffffffffu, mx0, o));
        mx1 = fmaxf(mx1, __shfl_down_sync(0xffffffffu, mx1, o));
        mx2 = fmaxf(mx2, __shfl_down_sync(0xffffffffu, mx2, o));
    }
    __shared__ float s6[8][6];
    if ((t & 31) == 0) {
        int w = t >> 5;
        s6[w][0] = mn0; s6[w][1] = mn1; s6[w][2] = mn2;
        s6[w][3] = mx0; s6[w][4] = mx1; s6[w][5] = mx2;
    }
    __syncthreads();
    __shared__ float fin[4];
    if (t == 0) {
        float a0 = s6[0][0], a1 = s6[0][1], a2 = s6[0][2];
        float b0 = s6[0][3], b1 = s6[0][4], b2 = s6[0][5];
        for (int w = 1; w < 8; w++) {
            a0 = fminf(a0, s6[w][0]); a1 = fminf(a1, s6[w][1]); a2 = fminf(a2, s6[w][2]);
            b0 = fmaxf(b0, s6[w][3]); b1 = fmaxf(b1, s6[w][4]); b2 = fmaxf(b2, s6[w][5]);
        }
        float d0 = __fsub_rn(b0, a0), d1 = __fsub_rn(b1, a1), d2 = __fsub_rn(b2, a2);
        float diff = fmaxf(fmaxf(d0, d1), d2);
        fin[0] = a0; fin[1] = a1; fin[2] = a2; fin[3] = diff;
        out[VMIN_OFF + p * 3 + 0] = a0;
        out[VMIN_OFF + p * 3 + 1] = a1;
        out[VMIN_OFF + p * 3 + 2] = a2;
        out[DIFF_OFF + p] = diff;
    }
    __syncthreads();
    float vx = fin[0], vy = fin[1], vz = fin[2], df = fin[3];
    for (int i = t; i < N_; i += 256) {
        float* o3 = g_pn + ((size_t)p * N_ + i) * 3;
        o3[0] = __fdiv_rn(__fsub_rn(base[i * 3 + 0], vx), df);
        o3[1] = __fdiv_rn(__fsub_rn(base[i * 3 + 1], vy), df);
        o3[2] = __fdiv_rn(__fsub_rn(base[i * 3 + 2], vz), df);
    }
    // pass-through outputs
    if (t < 3) out[POSG_OFF + p * 3 + t] = 0.0f;
    if (t == 0) out[BATCHG_OFF + p] = (float)p;
    for (int i = t; i < M2_; i += 256) out[BATCH2_OFF + p * M2_ + i] = (float)p;
    // zero xg region for later atomicMax
    for (int i = t; i < 768; i += 256) out[XG_OFF + p * 768 + i] = 0.0f;
}

// ---------------------------------------------------------------------------
// Kernel 2: farthest point sampling (one block per patch, sequential argmax)
// key = (float_bits(d) << 32) | (NPTS - idx): max-d, tie -> lowest idx
// src_sel: 0 -> g_pn, 1 -> g_q1.  q_ext: output (NULL -> g_q1)
// ---------------------------------------------------------------------------
template <int NPTS, int M>
__global__ __launch_bounds__(512) void fps_kernel(int src_sel, float* q_ext) {
    constexpr int T = 512;
    constexpr int U = NPTS / T;
    __shared__ float spx[NPTS], spy[NPTS], spz[NPTS];
    __shared__ unsigned long long wred[16];
    __shared__ int sj;
    int p = blockIdx.x, t = threadIdx.x;
    const float* base = (src_sel ? g_q1 : g_pn) + (size_t)p * NPTS * 3;
    float* q_out = (q_ext ? q_ext : g_q1) + (size_t)p * M * 3;
    for (int i = t; i < NPTS; i += T) {
        spx[i] = base[i * 3 + 0];
        spy[i] = base[i * 3 + 1];
        spz[i] = base[i * 3 + 2];
    }
    __syncthreads();
    float mx[U], my[U], mz[U], d[U];
    float x0 = spx[0], y0 = spy[0], z0 = spz[0];
#pragma unroll
    for (int u = 0; u < U; u++) {
        int i = t + u * T;
        mx[u] = spx[i]; my[u] = spy[i]; mz[u] = spz[i];
        d[u] = dist2e(mx[u], my[u], mz[u], x0, y0, z0);
    }
    if (t == 0) { q_out[0] = x0; q_out[1] = y0; q_out[2] = z0; }
    for (int it = 1; it < M; it++) {
        unsigned long long best = 0ull;
#pragma unroll
        for (int u = 0; u < U; u++) {
            unsigned long long key =
                ((unsigned long long)__float_as_uint(d[u]) << 32) |
                (unsigned)(NPTS - (t + u * T));
            if (key > best) best = key;
        }
#pragma unroll
        for (int o = 16; o; o >>= 1) {
            unsigned long long v = __shfl_down_sync(0xffffffffu, best, o);
            if (v > best) best = v;
        }
        if ((t & 31) == 0) wred[t >> 5] = best;
        __syncthreads();
        if (t < 32) {
            unsigned long long b = (t < 16) ? wred[t] : 0ull;
#pragma unroll
            for (int o = 8; o; o >>= 1) {
                unsigned long long v = __shfl_down_sync(0xffffffffu, b, o);
                if (v > b) b = v;
            }
            if (t == 0) sj = NPTS - (int)(unsigned)(b & 0xffffffffull);
        }
        __syncthreads();
        int j = sj;
        float jx = spx[j], jy = spy[j], jz = spz[j];
        if (t == 0) {
            q_out[it * 3 + 0] = jx; q_out[it * 3 + 1] = jy; q_out[it * 3 + 2] = jz;
        }
#pragma unroll
        for (int u = 0; u < U; u++) {
            float nd = dist2e(mx[u], my[u], mz[u], jx, jy, jz);
            d[u] = fminf(d[u], nd);
        }
        __syncthreads();
    }
}

// ---------------------------------------------------------------------------
// Kernel 3: radius K-nearest (stable insertion sort, lower index wins ties)
// src_sel: 0 -> pts=g_pn, 1 -> pts=g_q1.  lvl selects (nidx,cnt) buffers.
// ---------------------------------------------------------------------------
template <int NPTS>
__global__ void nbr_kernel(int src_sel, const float* __restrict__ q_ext,
                           int nq, float r2, int lvl) {
    __shared__ float spx[NPTS], spy[NPTS], spz[NPTS];
    int p = blockIdx.x, t = threadIdx.x;
    const float* base = (src_sel ? g_q1 : g_pn) + (size_t)p * NPTS * 3;
    const float* q = (q_ext ? q_ext : g_q1);
    int* nidx = lvl ? g_nidx2 : g_nidx1;
    int* ncnt = lvl ? g_cnt2 : g_cnt1;
    for (int i = t; i < NPTS; i += blockDim.x) {
        spx[i] = base[i * 3 + 0];
        spy[i] = base[i * 3 + 1];
        spz[i] = base[i * 3 + 2];
    }
    __syncthreads();
    if (t >= nq) return;
    const float* qq = q + ((size_t)p * nq + t) * 3;
    float qx = qq[0], qy = qq[1], qz = qq[2];
    float da[K_];
    int ia[K_];
    int cnt = 0;
    for (int j = 0; j < NPTS; j++) {
        float d2 = dist2e(spx[j], spy[j], spz[j], qx, qy, qz);
        if (d2 <= r2) {
            if (cnt < K_) {
                int pos = cnt++;
                while (pos > 0 && da[pos - 1] > d2) {
                    da[pos] = da[pos - 1]; ia[pos] = ia[pos - 1]; pos--;
                }
                da[pos] = d2; ia[pos] = j;
            } else if (d2 < da[K_ - 1]) {
                int pos = K_ - 1;
                while (pos > 0 && da[pos - 1] > d2) {
                    da[pos] = da[pos - 1]; ia[pos] = ia[pos - 1]; pos--;
                }
                da[pos] = d2; ia[pos] = j;
            }
        }
    }
    int* outp = nidx + ((size_t)p * nq + t) * K_;
#pragma unroll
    for (int k = 0; k < K_; k++) outp[k] = (k < cnt) ? ia[k] : 0;
    ncnt[(size_t)p * nq + t] = cnt;
}

// ---------------------------------------------------------------------------
// Kernel 4: MLP1 (6 -> 64 relu -> 128 relu) + masked warp-max per query
// One warp == one query, one lane == one neighbor; hidden row in registers.
// ---------------------------------------------------------------------------
__global__ __launch_bounds__(256) void mlp1_kernel(const float* __restrict__ W1a,
                                                   const float* __restrict__ b1a,
                                                   const float* __restrict__ W1b,
                                                   const float* __restrict__ b1b) {
    __shared__ __align__(16) float sWa[6 * 64];
    __shared__ __align__(16) float sba[64];
    __shared__ __align__(16) float sWb[64 * 128];
    __shared__ __align__(16) float sbb[128];
    int t = threadIdx.x;
    for (int i = t; i < 6 * 64; i += 256) sWa[i] = W1a[i];
    for (int i = t; i < 64; i += 256) sba[i] = b1a[i];
    for (int i = t; i < 64 * 128; i += 256) sWb[i] = W1b[i];
    for (int i = t; i < 128; i += 256) sbb[i] = b1b[i];
    __syncthreads();

    int gq = blockIdx.x * 8 + (t >> 5);   // global query id [0, 32768)
    int k = t & 31;
    int p = gq >> 9;
    int cnt = g_cnt1[gq];
    bool valid = (k < cnt);
    float f0 = 0, f1 = 0, f2 = 0, f3 = 0, f4 = 0, f5 = 0;
    {
        int j = g_nidx1[(size_t)gq * K_ + k];
        const float* pj = g_pn + ((size_t)p * N_ + j) * 3;
        const float* qc = g_q1 + (size_t)gq * 3;
        f0 = pj[0]; f1 = pj[1]; f2 = pj[2];
        f3 = f0 - qc[0]; f4 = f1 - qc[1]; f5 = f2 - qc[2];
    }
    float h[64];
#pragma unroll
    for (int c = 0; c < 64; c += 4) {
        float4 b4 = *(const float4*)&sba[c];
        float s0 = b4.x, s1 = b4.y, s2 = b4.z, s3 = b4.w;
#pragma unroll
        for (int i = 0; i < 6; i++) {
            float fv = (i == 0) ? f0 : (i == 1) ? f1 : (i == 2) ? f2
                     : (i == 3) ? f3 : (i == 4) ? f4 : f5;
            float4 w = *(const float4*)&sWa[i * 64 + c];
            s0 = fmaf(fv, w.x, s0); s1 = fmaf(fv, w.y, s1);
            s2 = fmaf(fv, w.z, s2); s3 = fmaf(fv, w.w, s3);
        }
        h[c + 0] = fmaxf(s0, 0.f); h[c + 1] = fmaxf(s1, 0.f);
        h[c + 2] = fmaxf(s2, 0.f); h[c + 3] = fmaxf(s3, 0.f);
    }
    float* xo = g_x1 + (size_t)gq * 128;
#pragma unroll 2
    for (int c = 0; c < 128; c += 4) {
        float4 b4 = *(const float4*)&sbb[c];
        float s0 = b4.x, s1 = b4.y, s2 = b4.z, s3 = b4.w;
#pragma unroll
        for (int i = 0; i < 64; i++) {
            float4 w = *(const float4*)&sWb[i * 128 + c];
            float hv = h[i];
            s0 = fmaf(hv, w.x, s0); s1 = fmaf(hv, w.y, s1);
            s2 = fmaf(hv, w.z, s2); s3 = fmaf(hv, w.w, s3);
        }
        s0 = fmaxf(s0, 0.f); s1 = fmaxf(s1, 0.f);
        s2 = fmaxf(s2, 0.f); s3 = fmaxf(s3, 0.f);
        if (!valid) { s0 = s1 = s2 = s3 = 0.f; }
        unsigned m0 = __reduce_max_sync(0xffffffffu, __float_as_uint(s0));
        unsigned m1 = __reduce_max_sync(0xffffffffu, __float_as_uint(s1));
        unsigned m2 = __reduce_max_sync(0xffffffffu, __float_as_uint(s2));
        unsigned m3 = __reduce_max_sync(0xffffffffu, __float_as_uint(s3));
        if (k == 0) {
            xo[c + 0] = __uint_as_float(m0);
            xo[c + 1] = __uint_as_float(m1);
            xo[c + 2] = __uint_as_float(m2);
            xo[c + 3] = __uint_as_float(m3);
        }
    }
}

// ---------------------------------------------------------------------------
// Kernel 5: MLP2 (131 -> 256 relu -> 384 relu) + masked max over K neighbors
// One block per query (8192 blocks, 256 threads). Transposed smem layout:
// featT[i*36+k], h1T[c*36+k]  -> float4 broadcast reads in neighbor loop.
// Dynamic smem: (131+256)*36*4 = 55728 bytes.
// ---------------------------------------------------------------------------
#define MLP2_SMEM ((131 + 256) * 36 * 4)
__global__ __launch_bounds__(256) void mlp2_kernel(const float* __restrict__ q2,
                                                   const float* __restrict__ W2a,
                                                   const float* __restrict__ b2a,
                                                   const float* __restrict__ W2b,
                                                   const float* __restrict__ b2b,
                                                   float* __restrict__ out) {
    extern __shared__ __align__(16) float sm[];
    float* featT = sm;               // [131][36] (k-minor)
    float* h1T   = sm + 131 * 36;    // [256][36]
    int q = blockIdx.x;              // 0..8191
    int p = q >> 7;
    int t = threadIdx.x;
    int cnt = g_cnt2[q];
    int base_q1 = p * M1_;
    float q2x = q2[q * 3 + 0], q2y = q2[q * 3 + 1], q2z = q2[q * 3 + 2];
    // load features: x1 (128) and pj - q2 (3) per neighbor
    for (int e = t; e < K_ * 131; e += 256) {
        int k = e / 131, i = e - k * 131;
        int j = g_nidx2[q * K_ + k];
        float v;
        if (i < 128) {
            v = g_x1[((size_t)(base_q1 + j)) * 128 + i];
        } else {
            float c = (i == 128) ? q2x : (i == 129) ? q2y : q2z;
            v = g_q1[((size_t)(base_q1 + j)) * 3 + (i - 128)] - c;
        }
        featT[i * 36 + k] = v;
    }
    __syncthreads();
    // layer 1: channel c = t
    float s[K_];
    {
        float bc = b2a[t];
#pragma unroll
        for (int k = 0; k < K_; k++) s[k] = bc;
        for (int i = 0; i < 131; i++) {
            float w = W2a[i * 256 + t];
            const float4* fr = (const float4*)&featT[i * 36];
#pragma unroll
            for (int k4 = 0; k4 < 8; k4++) {
                float4 f = fr[k4];
                s[k4 * 4 + 0] = fmaf(f.x, w, s[k4 * 4 + 0]);
                s[k4 * 4 + 1] = fmaf(f.y, w, s[k4 * 4 + 1]);
                s[k4 * 4 + 2] = fmaf(f.z, w, s[k4 * 4 + 2]);
                s[k4 * 4 + 3] = fmaf(f.w, w, s[k4 * 4 + 3]);
            }
        }
        float4* hw = (float4*)&h1T[t * 36];
#pragma unroll
        for (int k4 = 0; k4 < 8; k4++) {
            float4 v;
            v.x = fmaxf(s[k4 * 4 + 0], 0.f);
            v.y = fmaxf(s[k4 * 4 + 1], 0.f);
            v.z = fmaxf(s[k4 * 4 + 2], 0.f);
            v.w = fmaxf(s[k4 * 4 + 3], 0.f);
            hw[k4] = v;
        }
    }
    __syncthreads();
    // layer 2: channels t and t+256 (if < 384)
#pragma unroll
    for (int pass = 0; pass < 2; pass++) {
        int c = t + pass * 256;
        if (c < 384) {
            float bc = b2b[c];
#pragma unroll
            for (int k = 0; k < K_; k++) s[k] = bc;
            for (int i = 0; i < 256; i++) {
                float w = W2b[i * 384 + c];
                const float4* hr = (const float4*)&h1T[i * 36];
#pragma unroll
                for (int k4 = 0; k4 < 8; k4++) {
                    float4 f = hr[k4];
                    s[k4 * 4 + 0] = fmaf(f.x, w, s[k4 * 4 + 0]);
                    s[k4 * 4 + 1] = fmaf(f.y, w, s[k4 * 4 + 1]);
                    s[k4 * 4 + 2] = fmaf(f.z, w, s[k4 * 4 + 2]);
                    s[k4 * 4 + 3] = fmaf(f.w, w, s[k4 * 4 + 3]);
                }
            }
            float m = 0.f;
            for (int k = 0; k < cnt; k++) m = fmaxf(m, fmaxf(s[k], 0.f));
            out[X2_OFF + (size_t)q * 384 + c] = m;
        }
    }
}

// ---------------------------------------------------------------------------
// Kernel 6: MLP3 (387 -> 512 relu -> 768 relu) + global max pool via atomics
// 8 queries per block (1024 blocks, 256 threads). Transposed smem (stride 8).
// ---------------------------------------------------------------------------
__global__ __launch_bounds__(256) void mlp3_kernel(const float* __restrict__ W3a,
                                                   const float* __restrict__ b3a,
                                                   const float* __restrict__ W3b,
                                                   const float* __restrict__ b3b,
                                                   float* __restrict__ out) {
    __shared__ __align__(16) float featT[387 * 8];  // [i][qq]
    __shared__ __align__(16) float hT[512 * 8];     // [i][qq]
    int b = blockIdx.x, t = threadIdx.x;
    int qbase = b * 8;
    int p = qbase >> 7;
    for (int e = t; e < 8 * 387; e += 256) {
        int qq = e / 387, i = e - qq * 387;
        int q = qbase + qq;
        float v = (i < 384) ? out[X2_OFF + (size_t)q * 384 + i]
                            : out[Q2_OFF + (size_t)q * 3 + (i - 384)];
        featT[i * 8 + qq] = v;
    }
    __syncthreads();
    // layer 1: channels t and t+256
    {
        float s0[8], s1[8];
        float bc0 = b3a[t], bc1 = b3a[t + 256];
#pragma unroll
        for (int qq = 0; qq < 8; qq++) { s0[qq] = bc0; s1[qq] = bc1; }
        for (int i = 0; i < 387; i++) {
            float w0 = W3a[i * 512 + t];
            float w1 = W3a[i * 512 + t + 256];
            const float4* fr = (const float4*)&featT[i * 8];
            float4 fa = fr[0], fb = fr[1];
            s0[0] = fmaf(fa.x, w0, s0[0]); s1[0] = fmaf(fa.x, w1, s1[0]);
            s0[1] = fmaf(fa.y, w0, s0[1]); s1[1] = fmaf(fa.y, w1, s1[1]);
            s0[2] = fmaf(fa.z, w0, s0[2]); s1[2] = fmaf(fa.z, w1, s1[2]);
            s0[3] = fmaf(fa.w, w0, s0[3]); s1[3] = fmaf(fa.w, w1, s1[3]);
            s0[4] = fmaf(fb.x, w0, s0[4]); s1[4] = fmaf(fb.x, w1, s1[4]);
            s0[5] = fmaf(fb.y, w0, s0[5]); s1[5] = fmaf(fb.y, w1, s1[5]);
            s0[6] = fmaf(fb.z, w0, s0[6]); s1[6] = fmaf(fb.z, w1, s1[6]);
            s0[7] = fmaf(fb.w, w0, s0[7]); s1[7] = fmaf(fb.w, w1, s1[7]);
        }
        float4* h0 = (float4*)&hT[t * 8];
        float4* h1 = (float4*)&hT[(t + 256) * 8];
        float4 v;
        v.x = fmaxf(s0[0], 0.f); v.y = fmaxf(s0[1], 0.f);
        v.z = fmaxf(s0[2], 0.f); v.w = fmaxf(s0[3], 0.f); h0[0] = v;
        v.x = fmaxf(s0[4], 0.f); v.y = fmaxf(s0[5], 0.f);
        v.z = fmaxf(s0[6], 0.f); v.w = fmaxf(s0[7], 0.f); h0[1] = v;
        v.x = fmaxf(s1[0], 0.f); v.y = fmaxf(s1[1], 0.f);
        v.z = fmaxf(s1[2], 0.f); v.w = fmaxf(s1[3], 0.f); h1[0] = v;
        v.x = fmaxf(s1[4], 0.f); v.y = fmaxf(s1[5], 0.f);
        v.z = fmaxf(s1[6], 0.f); v.w = fmaxf(s1[7], 0.f); h1[1] = v;
    }
    __syncthreads();
    // layer 2: channels t, t+256, t+512; local max over 8 queries; atomicMax
    {
        float s0[8], s1[8], s2[8];
        float bc0 = b3b[t], bc1 = b3b[t + 256], bc2 = b3b[t + 512];
#pragma unroll
        for (int qq = 0; qq < 8; qq++) { s0[qq] = bc0; s1[qq] = bc1; s2[qq] = bc2; }
        for (int i = 0; i < 512; i++) {
            float w0 = W3b[i * 768 + t];
            float w1 = W3b[i * 768 + t + 256];
            float w2 = W3b[i * 768 + t + 512];
            const float4* hr = (const float4*)&hT[i * 8];
            float4 fa = hr[0], fb = hr[1];
            s0[0] = fmaf(fa.x, w0, s0[0]); s1[0] = fmaf(fa.x, w1, s1[0]); s2[0] = fmaf(fa.x, w2, s2[0]);
            s0[1] = fmaf(fa.y, w0, s0[1]); s1[1] = fmaf(fa.y, w1, s1[1]); s2[1] = fmaf(fa.y, w2, s2[1]);
            s0[2] = fmaf(fa.z, w0, s0[2]); s1[2] = fmaf(fa.z, w1, s1[2]); s2[2] = fmaf(fa.z, w2, s2[2]);
            s0[3] = fmaf(fa.w, w0, s0[3]); s1[3] = fmaf(fa.w, w1, s1[3]); s2[3] = fmaf(fa.w, w2, s2[3]);
            s0[4] = fmaf(fb.x, w0, s0[4]); s1[4] = fmaf(fb.x, w1, s1[4]); s2[4] = fmaf(fb.x, w2, s2[4]);
            s0[5] = fmaf(fb.y, w0, s0[5]); s1[5] = fmaf(fb.y, w1, s1[5]); s2[5] = fmaf(fb.y, w2, s2[5]);
            s0[6] = fmaf(fb.z, w0, s0[6]); s1[6] = fmaf(fb.z, w1, s1[6]); s2[6] = fmaf(fb.z, w2, s2[6]);
            s0[7] = fmaf(fb.w, w0, s0[7]); s1[7] = fmaf(fb.w, w1, s1[7]); s2[7] = fmaf(fb.w, w2, s2[7]);
        }
        float m0 = 0.f, m1 = 0.f, m2 = 0.f;
#pragma unroll
        for (int qq = 0; qq < 8; qq++) {
            m0 = fmaxf(m0, fmaxf(s0[qq], 0.f));
            m1 = fmaxf(m1, fmaxf(s1[qq], 0.f));
            m2 = fmaxf(m2, fmaxf(s2[qq], 0.f));
        }
        atomicMax((unsigned*)&out[XG_OFF + (size_t)p * 768 + t], __float_as_uint(m0));
        atomicMax((unsigned*)&out[XG_OFF + (size_t)p * 768 + t + 256], __float_as_uint(m1));
        atomicMax((unsigned*)&out[XG_OFF + (size_t)p * 768 + t + 512], __float_as_uint(m2));
    }
}

// ---------------------------------------------------------------------------
// Launch
// ---------------------------------------------------------------------------
extern "C" void kernel_launch(void* const* d_in, const int* in_sizes, int n_in,
                              void* d_out, int out_size) {
    const float* pos = (const float*)d_in[0];
    // d_in[1] = pi (unused)
    const float* W1a = (const float*)d_in[2];
    const float* b1a = (const float*)d_in[3];
    const float* W1b = (const float*)d_in[4];
    const float* b1b = (const float*)d_in[5];
    const float* W2a = (const float*)d_in[6];
    const float* b2a = (const float*)d_in[7];
    const float* W2b = (const float*)d_in[8];
    const float* b2b = (const float*)d_in[9];
    const float* W3a = (const float*)d_in[10];
    const float* b3a = (const float*)d_in[11];
    const float* W3b = (const float*)d_in[12];
    const float* b3b = (const float*)d_in[13];
    float* out = (float*)d_out;

    const float R1SQ = (float)(0.15 * 0.15);
    const float R2SQ = (float)(0.3 * 0.3);

    static bool attr_set = false;
    if (!attr_set) {
        cudaFuncSetAttribute(mlp2_kernel, cudaFuncAttributeMaxDynamicSharedMemorySize,
                             MLP2_SMEM);
        attr_set = true;
    }

    norm_kernel<<<P_, 256>>>(pos, out);
    fps_kernel<N_, M1_><<<P_, 512>>>(0, nullptr);
    nbr_kernel<N_><<<P_, 512>>>(0, nullptr, M1_, R1SQ, 0);
    mlp1_kernel<<<P_ * M1_ / 8, 256>>>(W1a, b1a, W1b, b1b);
    fps_kernel<M1_, M2_><<<P_, 512>>>(1, out + Q2_OFF);
    nbr_kernel<M1_><<<P_, 128>>>(1, out + Q2_OFF, M2_, R2SQ, 1);
    mlp2_kernel<<<P_ * M2_, 256, MLP2_SMEM>>>(out + Q2_OFF, W2a, b2a, W2b, b2b, out);
    mlp3_kernel<<<P_ * M2_ / 8, 256>>>(W3a, b3a, W3b, b3b, out);
}

// round 3
// speedup vs baseline: 1.7996x; 1.7996x over previous
#include <cuda_runtime.h>

// ---------------------------------------------------------------------------
// Problem constants
// ---------------------------------------------------------------------------
#define P_ 64
#define N_ 2048
#define M1_ 512
#define M2_ 128
#define K_ 32

// Output packing offsets (float32 elements, reference tuple order)
#define XG_OFF      0            // [64,768]
#define POSG_OFF    49152        // [64,3] zeros
#define BATCHG_OFF  49344        // [64]
#define X2_OFF      49408        // [8192,384]
#define Q2_OFF      3195136      // [8192,3]
#define BATCH2_OFF  3219712      // [8192]
#define VMIN_OFF    3227904      // [64,3]
#define DIFF_OFF    3228096      // [64]

typedef unsigned long long u64;

// ---------------------------------------------------------------------------
// Scratch (device globals; no allocations allowed)
// ---------------------------------------------------------------------------
__device__ float g_pn   [P_ * N_ * 3];
__device__ float g_q1   [P_ * M1_ * 3];
__device__ int   g_nidx1[P_ * M1_ * K_];
__device__ int   g_cnt1 [P_ * M1_];
__device__ float g_x1   [P_ * M1_ * 128];
__device__ int   g_nidx2[P_ * M2_ * K_];
__device__ int   g_cnt2 [P_ * M2_];

// ---------------------------------------------------------------------------
// f32x2 packed helpers (sm_103a FFMA2 path — PTX-only per SASS_QUICKREF)
// ---------------------------------------------------------------------------
__device__ __forceinline__ u64 ffma2(u64 a, u64 b, u64 c) {
    u64 d;
    asm("fma.rn.f32x2 %0, %1, %2, %3;" : "=l"(d) : "l"(a), "l"(b), "l"(c));
    return d;
}
__device__ __forceinline__ u64 pack2(float x, float y) {
    u64 r;
    asm("mov.b64 %0, {%1, %2};" : "=l"(r) : "f"(x), "f"(y));
    return r;
}
__device__ __forceinline__ float2 unpk(u64 v) {
    float2 r;
    asm("mov.b64 {%0, %1}, %2;" : "=f"(r.x), "=f"(r.y) : "l"(v));
    return r;
}

// ---------------------------------------------------------------------------
// Exact (non-fused) squared distance: ((dx*dx + dy*dy) + dz*dz)
// ---------------------------------------------------------------------------
__device__ __forceinline__ float dist2e(float ax, float ay, float az,
                                        float bx, float by, float bz) {
    float dx = __fsub_rn(ax, bx);
    float dy = __fsub_rn(ay, by);
    float dz = __fsub_rn(az, bz);
    float s  = __fadd_rn(__fmul_rn(dx, dx), __fmul_rn(dy, dy));
    return __fadd_rn(s, __fmul_rn(dz, dz));
}

// ---------------------------------------------------------------------------
// Kernel 1: per-patch normalization + small pass-through outputs + zero xg
// ---------------------------------------------------------------------------
__global__ __launch_bounds__(256) void norm_kernel(const float* __restrict__ pos,
                                                   float* __restrict__ out) {
    int p = blockIdx.x, t = threadIdx.x;
    const float* base = pos + (size_t)p * N_ * 3;

    float mn0 = 3.4e38f, mn1 = 3.4e38f, mn2 = 3.4e38f;
    float mx0 = -3.4e38f, mx1 = -3.4e38f, mx2 = -3.4e38f;
    for (int i = t; i < N_; i += 256) {
        float v0 = base[i * 3 + 0], v1 = base[i * 3 + 1], v2 = base[i * 3 + 2];
        mn0 = fminf(mn0, v0); mx0 = fmaxf(mx0, v0);
        mn1 = fminf(mn1, v1); mx1 = fmaxf(mx1, v1);
        mn2 = fminf(mn2, v2); mx2 = fmaxf(mx2, v2);
    }
#pragma unroll
    for (int o = 16; o; o >>= 1) {
        mn0 = fminf(mn0, __shfl_down_sync(0xffffffffu, mn0, o));
        mn1 = fminf(mn1, __shfl_down_sync(0xffffffffu, mn1, o));
        mn2 = fminf(mn2, __shfl_down_sync(0xffffffffu, mn2, o));
        mx0 = fmaxf(mx0, __shfl_down_sync(0xffffffffu, mx0, o));
        mx1 = fmaxf(mx1, __shfl_down_sync(0xffffffffu, mx1, o));
        mx2 = fmaxf(mx2, __shfl_down_sync(0xffffffffu, mx2, o));
    }
    __shared__ float s6[8][6];
    if ((t & 31) == 0) {
        int w = t >> 5;
        s6[w][0] = mn0; s6[w][1] = mn1; s6[w][2] = mn2;
        s6[w][3] = mx0; s6[w][4] = mx1; s6[w][5] = mx2;
    }
    __syncthreads();
    __shared__ float fin[4];
    if (t == 0) {
        float a0 = s6[0][0], a1 = s6[0][1], a2 = s6[0][2];
        float b0 = s6[0][3], b1 = s6[0][4], b2 = s6[0][5];
        for (int w = 1; w < 8; w++) {
            a0 = fminf(a0, s6[w][0]); a1 = fminf(a1, s6[w][1]); a2 = fminf(a2, s6[w][2]);
            b0 = fmaxf(b0, s6[w][3]); b1 = fmaxf(b1, s6[w][4]); b2 = fmaxf(b2, s6[w][5]);
        }
        float d0 = __fsub_rn(b0, a0), d1 = __fsub_rn(b1, a1), d2 = __fsub_rn(b2, a2);
        float diff = fmaxf(fmaxf(d0, d1), d2);
        fin[0] = a0; fin[1] = a1; fin[2] = a2; fin[3] = diff;
        out[VMIN_OFF + p * 3 + 0] = a0;
        out[VMIN_OFF + p * 3 + 1] = a1;
        out[VMIN_OFF + p * 3 + 2] = a2;
        out[DIFF_OFF + p] = diff;
    }
    __syncthreads();
    float vx = fin[0], vy = fin[1], vz = fin[2], df = fin[3];
    for (int i = t; i < N_; i += 256) {
        float* o3 = g_pn + ((size_t)p * N_ + i) * 3;
        o3[0] = __fdiv_rn(__fsub_rn(base[i * 3 + 0], vx), df);
        o3[1] = __fdiv_rn(__fsub_rn(base[i * 3 + 1], vy), df);
        o3[2] = __fdiv_rn(__fsub_rn(base[i * 3 + 2], vz), df);
    }
    if (t < 3) out[POSG_OFF + p * 3 + t] = 0.0f;
    if (t == 0) out[BATCHG_OFF + p] = (float)p;
    for (int i = t; i < M2_; i += 256) out[BATCH2_OFF + p * M2_ + i] = (float)p;
    for (int i = t; i < 768; i += 256) out[XG_OFF + p * 768 + i] = 0.0f;
}

// ---------------------------------------------------------------------------
// Kernel 2: farthest point sampling (one block per patch, sequential argmax)
// ---------------------------------------------------------------------------
template <int NPTS, int M>
__global__ __launch_bounds__(512) void fps_kernel(int src_sel, float* q_ext) {
    constexpr int T = 512;
    constexpr int U = NPTS / T;
    __shared__ float spx[NPTS], spy[NPTS], spz[NPTS];
    __shared__ unsigned long long wred[16];
    __shared__ int sj;
    int p = blockIdx.x, t = threadIdx.x;
    const float* base = (src_sel ? g_q1 : g_pn) + (size_t)p * NPTS * 3;
    float* q_out = (q_ext ? q_ext : g_q1) + (size_t)p * M * 3;
    for (int i = t; i < NPTS; i += T) {
        spx[i] = base[i * 3 + 0];
        spy[i] = base[i * 3 + 1];
        spz[i] = base[i * 3 + 2];
    }
    __syncthreads();
    float mx[U], my[U], mz[U], d[U];
    float x0 = spx[0], y0 = spy[0], z0 = spz[0];
#pragma unroll
    for (int u = 0; u < U; u++) {
        int i = t + u * T;
        mx[u] = spx[i]; my[u] = spy[i]; mz[u] = spz[i];
        d[u] = dist2e(mx[u], my[u], mz[u], x0, y0, z0);
    }
    if (t == 0) { q_out[0] = x0; q_out[1] = y0; q_out[2] = z0; }
    for (int it = 1; it < M; it++) {
        unsigned long long best = 0ull;
#pragma unroll
        for (int u = 0; u < U; u++) {
            unsigned long long key =
                ((unsigned long long)__float_as_uint(d[u]) << 32) |
                (unsigned)(NPTS - (t + u * T));
            if (key > best) best = key;
        }
#pragma unroll
        for (int o = 16; o; o >>= 1) {
            unsigned long long v = __shfl_down_sync(0xffffffffu, best, o);
            if (v > best) best = v;
        }
        if ((t & 31) == 0) wred[t >> 5] = best;
        __syncthreads();
        if (t < 32) {
            unsigned long long b = (t < 16) ? wred[t] : 0ull;
#pragma unroll
            for (int o = 8; o; o >>= 1) {
                unsigned long long v = __shfl_down_sync(0xffffffffu, b, o);
                if (v > b) b = v;
            }
            if (t == 0) sj = NPTS - (int)(unsigned)(b & 0xffffffffull);
        }
        __syncthreads();
        int j = sj;
        float jx = spx[j], jy = spy[j], jz = spz[j];
        if (t == 0) {
            q_out[it * 3 + 0] = jx; q_out[it * 3 + 1] = jy; q_out[it * 3 + 2] = jz;
        }
#pragma unroll
        for (int u = 0; u < U; u++) {
            float nd = dist2e(mx[u], my[u], mz[u], jx, jy, jz);
            d[u] = fminf(d[u], nd);
        }
        // no barrier needed here: BAR before wred-read and BAR before sj-read
        // already order the next iteration's wred/sj writes.
    }
}

// ---------------------------------------------------------------------------
// Kernel 3: radius top-K — branchless register top-K (no local memory).
// Keeps the K smallest (d2, j) lexicographic; strict '<' on eviction matches
// lax.top_k tie rule (earlier index survives). Output order is irrelevant
// (consumer is a max-pool over the neighbor set).
// ---------------------------------------------------------------------------
template <int NPTS>
__global__ void nbr_kernel(int src_sel, const float* __restrict__ q_ext,
                           int nq, float r2, int lvl) {
    __shared__ float spx[NPTS], spy[NPTS], spz[NPTS];
    int p = blockIdx.x, t = threadIdx.x;
    const float* base = (src_sel ? g_q1 : g_pn) + (size_t)p * NPTS * 3;
    const float* q = (q_ext ? q_ext : g_q1);
    int* nidx = lvl ? g_nidx2 : g_nidx1;
    int* ncnt = lvl ? g_cnt2 : g_cnt1;
    for (int i = t; i < NPTS; i += blockDim.x) {
        spx[i] = base[i * 3 + 0];
        spy[i] = base[i * 3 + 1];
        spz[i] = base[i * 3 + 2];
    }
    __syncthreads();
    if (t >= nq) return;
    const float* qq = q + ((size_t)p * nq + t) * 3;
    float qx = qq[0], qy = qq[1], qz = qq[2];

    float da[K_];
    int ia[K_];
#pragma unroll
    for (int k = 0; k < K_; k++) { da[k] = 3.4e38f; ia[k] = 0; }
    int cnt = 0;
    float maxd = 3.4e38f;
    int maxslot = 0;

    for (int j = 0; j < NPTS; j++) {
        float d2 = dist2e(spx[j], spy[j], spz[j], qx, qy, qz);
        if (d2 <= r2) {
            if (cnt < K_) {
#pragma unroll
                for (int k = 0; k < K_; k++)
                    if (k == cnt) { da[k] = d2; ia[k] = j; }
                cnt++;
                if (cnt == K_) {
                    float bd = da[0]; int bj = ia[0]; int bs = 0;
#pragma unroll
                    for (int k = 1; k < K_; k++) {
                        bool g = (da[k] > bd) || (da[k] == bd && ia[k] > bj);
                        if (g) { bd = da[k]; bj = ia[k]; bs = k; }
                    }
                    maxd = bd; maxslot = bs;
                }
            } else if (d2 < maxd) {
#pragma unroll
                for (int k = 0; k < K_; k++)
                    if (k == maxslot) { da[k] = d2; ia[k] = j; }
                float bd = da[0]; int bj = ia[0]; int bs = 0;
#pragma unroll
                for (int k = 1; k < K_; k++) {
                    bool g = (da[k] > bd) || (da[k] == bd && ia[k] > bj);
                    if (g) { bd = da[k]; bj = ia[k]; bs = k; }
                }
                maxd = bd; maxslot = bs;
            }
        }
    }
    int* outp = nidx + ((size_t)p * nq + t) * K_;
#pragma unroll
    for (int k = 0; k < K_; k++) outp[k] = (k < cnt) ? ia[k] : 0;
    ncnt[(size_t)p * nq + t] = cnt;
}

// ---------------------------------------------------------------------------
// Kernel 4: MLP1 (6 -> 64 relu -> 128 relu) + masked warp-max per query
// One warp == one query, one lane == one neighbor. FFMA2 in the 64x128 layer.
// ---------------------------------------------------------------------------
__global__ __launch_bounds__(256) void mlp1_kernel(const float* __restrict__ W1a,
                                                   const float* __restrict__ b1a,
                                                   const float* __restrict__ W1b,
                                                   const float* __restrict__ b1b) {
    __shared__ __align__(16) float sWa[6 * 64];
    __shared__ __align__(16) float sba[64];
    __shared__ __align__(16) float sWb[64 * 128];
    __shared__ __align__(16) float sbb[128];
    int t = threadIdx.x;
    for (int i = t; i < 6 * 64; i += 256) sWa[i] = W1a[i];
    for (int i = t; i < 64; i += 256) sba[i] = b1a[i];
    for (int i = t; i < 64 * 128; i += 256) sWb[i] = W1b[i];
    for (int i = t; i < 128; i += 256) sbb[i] = b1b[i];
    __syncthreads();

    int gq = blockIdx.x * 8 + (t >> 5);
    int k = t & 31;
    int p = gq >> 9;
    int cnt = g_cnt1[gq];
    bool valid = (k < cnt);
    float f0 = 0, f1 = 0, f2 = 0, f3 = 0, f4 = 0, f5 = 0;
    {
        int j = g_nidx1[(size_t)gq * K_ + k];
        const float* pj = g_pn + ((size_t)p * N_ + j) * 3;
        const float* qc = g_q1 + (size_t)gq * 3;
        f0 = pj[0]; f1 = pj[1]; f2 = pj[2];
        f3 = f0 - qc[0]; f4 = f1 - qc[1]; f5 = f2 - qc[2];
    }
    float h[64];
#pragma unroll
    for (int c = 0; c < 64; c += 4) {
        float4 b4 = *(const float4*)&sba[c];
        float s0 = b4.x, s1 = b4.y, s2 = b4.z, s3 = b4.w;
#pragma unroll
        for (int i = 0; i < 6; i++) {
            float fv = (i == 0) ? f0 : (i == 1) ? f1 : (i == 2) ? f2
                     : (i == 3) ? f3 : (i == 4) ? f4 : f5;
            float4 w = *(const float4*)&sWa[i * 64 + c];
            s0 = fmaf(fv, w.x, s0); s1 = fmaf(fv, w.y, s1);
            s2 = fmaf(fv, w.z, s2); s3 = fmaf(fv, w.w, s3);
        }
        h[c + 0] = fmaxf(s0, 0.f); h[c + 1] = fmaxf(s1, 0.f);
        h[c + 2] = fmaxf(s2, 0.f); h[c + 3] = fmaxf(s3, 0.f);
    }
    float* xo = g_x1 + (size_t)gq * 128;
#pragma unroll 1
    for (int cb = 0; cb < 16; cb++) {
        const ulonglong2* bb = (const ulonglong2*)&sbb[cb * 8];
        ulonglong2 b01 = bb[0], b23 = bb[1];
        u64 a0 = b01.x, a1 = b01.y, a2 = b23.x, a3 = b23.y;
#pragma unroll
        for (int i = 0; i < 64; i++) {
            u64 hv = pack2(h[i], h[i]);
            const ulonglong2* wr = (const ulonglong2*)&sWb[i * 128 + cb * 8];
            ulonglong2 wA = wr[0], wB = wr[1];
            a0 = ffma2(wA.x, hv, a0); a1 = ffma2(wA.y, hv, a1);
            a2 = ffma2(wB.x, hv, a2); a3 = ffma2(wB.y, hv, a3);
        }
        float2 v0 = unpk(a0), v1 = unpk(a1), v2 = unpk(a2), v3 = unpk(a3);
        float r[8] = {v0.x, v0.y, v1.x, v1.y, v2.x, v2.y, v3.x, v3.y};
        float m[8];
#pragma unroll
        for (int e = 0; e < 8; e++) {
            float s = valid ? fmaxf(r[e], 0.f) : 0.f;
            m[e] = __uint_as_float(__reduce_max_sync(0xffffffffu, __float_as_uint(s)));
        }
        if (k == 0) {
            ((float4*)&xo[cb * 8])[0] = make_float4(m[0], m[1], m[2], m[3]);
            ((float4*)&xo[cb * 8])[1] = make_float4(m[4], m[5], m[6], m[7]);
        }
    }
}

// ---------------------------------------------------------------------------
// Kernel 5: MLP2 (131 -> 256 relu -> 384 relu) + masked max over K neighbors
// One block per query. Channel-pair per thread + FFMA2 over neighbor pairs.
// featT[i][36] / h1T[c][36] transposed smem; rows 144B (16B aligned).
// ---------------------------------------------------------------------------
#define MLP2_SMEM ((131 + 256) * 36 * 4)
__global__ __launch_bounds__(256) void mlp2_kernel(const float* __restrict__ q2,
                                                   const float* __restrict__ W2a,
                                                   const float* __restrict__ b2a,
                                                   const float* __restrict__ W2b,
                                                   const float* __restrict__ b2b,
                                                   float* __restrict__ out) {
    extern __shared__ __align__(16) float sm[];
    float* featT = sm;               // [131][36]
    float* h1T   = sm + 131 * 36;    // [256][36]
    int q = blockIdx.x;
    int p = q >> 7;
    int t = threadIdx.x;
    int cnt = g_cnt2[q];
    int base_q1 = p * M1_;
    float q2x = q2[q * 3 + 0], q2y = q2[q * 3 + 1], q2z = q2[q * 3 + 2];
    for (int e = t; e < K_ * 131; e += 256) {
        int k = e / 131, i = e - k * 131;
        int j = g_nidx2[q * K_ + k];
        float v;
        if (i < 128) {
            v = g_x1[((size_t)(base_q1 + j)) * 128 + i];
        } else {
            float c = (i == 128) ? q2x : (i == 129) ? q2y : q2z;
            v = g_q1[((size_t)(base_q1 + j)) * 3 + (i - 128)] - c;
        }
        featT[i * 36 + k] = v;
    }
    __syncthreads();
    // layer 1: threads 0..127 each compute channel pair (2t, 2t+1)
    if (t < 128) {
        int c0 = 2 * t;
        float2 bp = *(const float2*)&b2a[c0];
        u64 a0[16], a1[16];
        u64 bx = pack2(bp.x, bp.x), by = pack2(bp.y, bp.y);
#pragma unroll
        for (int m = 0; m < 16; m++) { a0[m] = bx; a1[m] = by; }
        for (int i = 0; i < 131; i++) {
            float2 wv = *(const float2*)&W2a[i * 256 + c0];
            u64 w0 = pack2(wv.x, wv.x), w1 = pack2(wv.y, wv.y);
            const ulonglong2* fr = (const ulonglong2*)&featT[i * 36];
#pragma unroll
            for (int mm = 0; mm < 8; mm++) {
                ulonglong2 f = fr[mm];
                a0[2 * mm]     = ffma2(f.x, w0, a0[2 * mm]);
                a0[2 * mm + 1] = ffma2(f.y, w0, a0[2 * mm + 1]);
                a1[2 * mm]     = ffma2(f.x, w1, a1[2 * mm]);
                a1[2 * mm + 1] = ffma2(f.y, w1, a1[2 * mm + 1]);
            }
        }
        float4* h0 = (float4*)&h1T[c0 * 36];
        float4* h1 = (float4*)&h1T[(c0 + 1) * 36];
#pragma unroll
        for (int mm = 0; mm < 8; mm++) {
            float2 u0 = unpk(a0[2 * mm]), u1 = unpk(a0[2 * mm + 1]);
            h0[mm] = make_float4(fmaxf(u0.x, 0.f), fmaxf(u0.y, 0.f),
                                 fmaxf(u1.x, 0.f), fmaxf(u1.y, 0.f));
            float2 w0 = unpk(a1[2 * mm]), w1 = unpk(a1[2 * mm + 1]);
            h1[mm] = make_float4(fmaxf(w0.x, 0.f), fmaxf(w0.y, 0.f),
                                 fmaxf(w1.x, 0.f), fmaxf(w1.y, 0.f));
        }
    }
    __syncthreads();
    // layer 2: threads 0..191 each compute channel pair (2t, 2t+1) of 384
    if (t < 192) {
        int c0 = 2 * t;
        float2 bp = *(const float2*)&b2b[c0];
        u64 a0[16], a1[16];
        u64 bx = pack2(bp.x, bp.x), by = pack2(bp.y, bp.y);
#pragma unroll
        for (int m = 0; m < 16; m++) { a0[m] = bx; a1[m] = by; }
        for (int i = 0; i < 256; i++) {
            float2 wv = *(const float2*)&W2b[i * 384 + c0];
            u64 w0 = pack2(wv.x, wv.x), w1 = pack2(wv.y, wv.y);
            const ulonglong2* hr = (const ulonglong2*)&h1T[i * 36];
#pragma unroll
            for (int mm = 0; mm < 8; mm++) {
                ulonglong2 f = hr[mm];
                a0[2 * mm]     = ffma2(f.x, w0, a0[2 * mm]);
                a0[2 * mm + 1] = ffma2(f.y, w0, a0[2 * mm + 1]);
                a1[2 * mm]     = ffma2(f.x, w1, a1[2 * mm]);
                a1[2 * mm + 1] = ffma2(f.y, w1, a1[2 * mm + 1]);
            }
        }
        float m0 = 0.f, m1 = 0.f;
#pragma unroll
        for (int m = 0; m < 16; m++) {
            float2 u0 = unpk(a0[m]);
            float2 u1 = unpk(a1[m]);
            if (2 * m < cnt)     { m0 = fmaxf(m0, fmaxf(u0.x, 0.f)); m1 = fmaxf(m1, fmaxf(u1.x, 0.f)); }
            if (2 * m + 1 < cnt) { m0 = fmaxf(m0, fmaxf(u0.y, 0.f)); m1 = fmaxf(m1, fmaxf(u1.y, 0.f)); }
        }
        out[X2_OFF + (size_t)q * 384 + c0] = m0;
        out[X2_OFF + (size_t)q * 384 + c0 + 1] = m1;
    }
}

// ---------------------------------------------------------------------------
// Kernel 6: MLP3 (387 -> 512 relu -> 768 relu) + global max pool via atomics
// 8 queries per block; FFMA2 over query pairs.
// ---------------------------------------------------------------------------
__global__ __launch_bounds__(256) void mlp3_kernel(const float* __restrict__ W3a,
                                                   const float* __restrict__ b3a,
                                                   const float* __restrict__ W3b,
                                                   const float* __restrict__ b3b,
                                                   float* __restrict__ out) {
    __shared__ __align__(16) float featT[387 * 8];  // [i][qq], rows 32B
    __shared__ __align__(16) float hT[512 * 8];
    int b = blockIdx.x, t = threadIdx.x;
    int qbase = b * 8;
    int p = qbase >> 7;
    for (int e = t; e < 8 * 387; e += 256) {
        int qq = e / 387, i = e - qq * 387;
        int q = qbase + qq;
        float v = (i < 384) ? out[X2_OFF + (size_t)q * 384 + i]
                            : out[Q2_OFF + (size_t)q * 3 + (i - 384)];
        featT[i * 8 + qq] = v;
    }
    __syncthreads();
    {
        float bc0 = b3a[t], bc1 = b3a[t + 256];
        u64 s0[4], s1[4];
        u64 p0 = pack2(bc0, bc0), p1 = pack2(bc1, bc1);
#pragma unroll
        for (int m = 0; m < 4; m++) { s0[m] = p0; s1[m] = p1; }
        for (int i = 0; i < 387; i++) {
            float w0f = W3a[i * 512 + t];
            float w1f = W3a[i * 512 + t + 256];
            u64 w0 = pack2(w0f, w0f), w1 = pack2(w1f, w1f);
            const ulonglong2* fr = (const ulonglong2*)&featT[i * 8];
            ulonglong2 fa = fr[0], fb = fr[1];
            s0[0] = ffma2(fa.x, w0, s0[0]); s0[1] = ffma2(fa.y, w0, s0[1]);
            s0[2] = ffma2(fb.x, w0, s0[2]); s0[3] = ffma2(fb.y, w0, s0[3]);
            s1[0] = ffma2(fa.x, w1, s1[0]); s1[1] = ffma2(fa.y, w1, s1[1]);
            s1[2] = ffma2(fb.x, w1, s1[2]); s1[3] = ffma2(fb.y, w1, s1[3]);
        }
        float4* h0 = (float4*)&hT[t * 8];
        float4* h1 = (float4*)&hT[(t + 256) * 8];
        {
            float2 u0 = unpk(s0[0]), u1 = unpk(s0[1]), u2 = unpk(s0[2]), u3 = unpk(s0[3]);
            h0[0] = make_float4(fmaxf(u0.x, 0.f), fmaxf(u0.y, 0.f), fmaxf(u1.x, 0.f), fmaxf(u1.y, 0.f));
            h0[1] = make_float4(fmaxf(u2.x, 0.f), fmaxf(u2.y, 0.f), fmaxf(u3.x, 0.f), fmaxf(u3.y, 0.f));
        }
        {
            float2 u0 = unpk(s1[0]), u1 = unpk(s1[1]), u2 = unpk(s1[2]), u3 = unpk(s1[3]);
            h1[0] = make_float4(fmaxf(u0.x, 0.f), fmaxf(u0.y, 0.f), fmaxf(u1.x, 0.f), fmaxf(u1.y, 0.f));
            h1[1] = make_float4(fmaxf(u2.x, 0.f), fmaxf(u2.y, 0.f), fmaxf(u3.x, 0.f), fmaxf(u3.y, 0.f));
        }
    }
    __syncthreads();
    {
        float bc0 = b3b[t], bc1 = b3b[t + 256], bc2 = b3b[t + 512];
        u64 s0[4], s1[4], s2[4];
        u64 p0 = pack2(bc0, bc0), p1 = pack2(bc1, bc1), p2 = pack2(bc2, bc2);
#pragma unroll
        for (int m = 0; m < 4; m++) { s0[m] = p0; s1[m] = p1; s2[m] = p2; }
        for (int i = 0; i < 512; i++) {
            float w0f = W3b[i * 768 + t];
            float w1f = W3b[i * 768 + t + 256];
            float w2f = W3b[i * 768 + t + 512];
            u64 w0 = pack2(w0f, w0f), w1 = pack2(w1f, w1f), w2 = pack2(w2f, w2f);
            const ulonglong2* hr = (const ulonglong2*)&hT[i * 8];
            ulonglong2 fa = hr[0], fb = hr[1];
            s0[0] = ffma2(fa.x, w0, s0[0]); s0[1] = ffma2(fa.y, w0, s0[1]);
            s0[2] = ffma2(fb.x, w0, s0[2]); s0[3] = ffma2(fb.y, w0, s0[3]);
            s1[0] = ffma2(fa.x, w1, s1[0]); s1[1] = ffma2(fa.y, w1, s1[1]);
            s1[2] = ffma2(fb.x, w1, s1[2]); s1[3] = ffma2(fb.y, w1, s1[3]);
            s2[0] = ffma2(fa.x, w2, s2[0]); s2[1] = ffma2(fa.y, w2, s2[1]);
            s2[2] = ffma2(fb.x, w2, s2[2]); s2[3] = ffma2(fb.y, w2, s2[3]);
        }
        float m0 = 0.f, m1 = 0.f, m2 = 0.f;
#pragma unroll
        for (int m = 0; m < 4; m++) {
            float2 u0 = unpk(s0[m]), u1 = unpk(s1[m]), u2 = unpk(s2[m]);
            m0 = fmaxf(m0, fmaxf(fmaxf(u0.x, 0.f), fmaxf(u0.y, 0.f)));
            m1 = fmaxf(m1, fmaxf(fmaxf(u1.x, 0.f), fmaxf(u1.y, 0.f)));
            m2 = fmaxf(m2, fmaxf(fmaxf(u2.x, 0.f), fmaxf(u2.y, 0.f)));
        }
        atomicMax((unsigned*)&out[XG_OFF + (size_t)p * 768 + t], __float_as_uint(m0));
        atomicMax((unsigned*)&out[XG_OFF + (size_t)p * 768 + t + 256], __float_as_uint(m1));
        atomicMax((unsigned*)&out[XG_OFF + (size_t)p * 768 + t + 512], __float_as_uint(m2));
    }
}

// ---------------------------------------------------------------------------
// Launch
// ---------------------------------------------------------------------------
extern "C" void kernel_launch(void* const* d_in, const int* in_sizes, int n_in,
                              void* d_out, int out_size) {
    const float* pos = (const float*)d_in[0];
    const float* W1a = (const float*)d_in[2];
    const float* b1a = (const float*)d_in[3];
    const float* W1b = (const float*)d_in[4];
    const float* b1b = (const float*)d_in[5];
    const float* W2a = (const float*)d_in[6];
    const float* b2a = (const float*)d_in[7];
    const float* W2b = (const float*)d_in[8];
    const float* b2b = (const float*)d_in[9];
    const float* W3a = (const float*)d_in[10];
    const float* b3a = (const float*)d_in[11];
    const float* W3b = (const float*)d_in[12];
    const float* b3b = (const float*)d_in[13];
    float* out = (float*)d_out;

    const float R1SQ = (float)(0.15 * 0.15);
    const float R2SQ = (float)(0.3 * 0.3);

    static bool attr_set = false;
    if (!attr_set) {
        cudaFuncSetAttribute(mlp2_kernel, cudaFuncAttributeMaxDynamicSharedMemorySize,
                             MLP2_SMEM);
        attr_set = true;
    }

    norm_kernel<<<P_, 256>>>(pos, out);
    fps_kernel<N_, M1_><<<P_, 512>>>(0, nullptr);
    nbr_kernel<N_><<<P_, 512>>>(0, nullptr, M1_, R1SQ, 0);
    mlp1_kernel<<<P_ * M1_ / 8, 256>>>(W1a, b1a, W1b, b1b);
    fps_kernel<M1_, M2_><<<P_, 512>>>(1, out + Q2_OFF);
    nbr_kernel<M1_><<<P_, 128>>>(1, out + Q2_OFF, M2_, R2SQ, 1);
    mlp2_kernel<<<P_ * M2_, 256, MLP2_SMEM>>>(out + Q2_OFF, W2a, b2a, W2b, b2b, out);
    mlp3_kernel<<<P_ * M2_ / 8, 256>>>(W3a, b3a, W3b, b3b, out);
}